// round 13
// baseline (speedup 1.0000x reference)
#include <cuda_runtime.h>
#include <cuda_bf16.h>
#include <cstdint>

#define Bn   64
#define Nn   207
#define Tn   48
#define Fin  6
#define Hd   64
#define NSEQ (Bn * Nn)        // 13248

// scratch: GCN output / LSTM input, [seq][t][Hd]
__device__ float g_h2[(size_t)NSEQ * Tn * Hd];   // 162.8 MB

__device__ __forceinline__ float tanhm(float x) {
    float r; asm("tanh.approx.f32 %0, %1;" : "=f"(r) : "f"(x)); return r;
}
// sigmoid(x + b) with bh = 0.5*b precomputed
__device__ __forceinline__ float sigm2(float x, float bh) {
    return fmaf(tanhm(fmaf(x, 0.5f, bh)), 0.5f, 0.5f);
}
__device__ __forceinline__ uint32_t smem_u32(const void* p) {
    uint32_t a;
    asm("{ .reg .u64 t; cvta.to.shared.u64 t, %1; cvt.u32.u64 %0, t; }" : "=r"(a) : "l"(p));
    return a;
}

#define LDSM4(R, a) asm volatile("ldmatrix.sync.aligned.m8n8.x4.shared.b16 {%0,%1,%2,%3}, [%4];" \
    : "=r"((R)[0]), "=r"((R)[1]), "=r"((R)[2]), "=r"((R)[3]) : "r"(a))
#define LDSM2(R, a) asm volatile("ldmatrix.sync.aligned.m8n8.x2.shared.b16 {%0,%1}, [%2];" \
    : "=r"((R)[0]), "=r"((R)[1]) : "r"(a))
#define MMA16816(C, A, B) asm volatile( \
    "mma.sync.aligned.m16n8k16.row.col.f32.bf16.bf16.f32 " \
    "{%0,%1,%2,%3}, {%4,%5,%6,%7}, {%8,%9}, {%0,%1,%2,%3};" \
    : "+f"((C)[0]), "+f"((C)[1]), "+f"((C)[2]), "+f"((C)[3]) \
    : "r"((A)[0]), "r"((A)[1]), "r"((A)[2]), "r"((A)[3]), "r"((B)[0]), "r"((B)[1]))

__device__ __forceinline__ void bf16split(float v, unsigned short& h, unsigned short& l) {
    __nv_bfloat16 hb = __float2bfloat16(v);
    h = __bfloat16_as_ushort(hb);
    l = __bfloat16_as_ushort(__float2bfloat16(v - __bfloat162float(hb)));
}
__device__ __forceinline__ float bf16bits2f(uint32_t u) {
    return __uint_as_float(u << 16);
}

// =====================================================================
// Kernel 1: fused 2-layer GCN, z2 via HMMA.  grid (12, Bn), 256 thr,
// 4 timesteps per block.  A_hat[m][n] = (1 + (m==n)) / 208
// (unchanged — proven)
// =====================================================================
#define AR2 144
#define G_AHI   25760
#define G_ALO   55712
#define G_BHI   85664
#define G_BLO   94880
#define G_SMEM  104096

__global__ void __launch_bounds__(256, 2) gcn_kernel(
    const float* __restrict__ x,  const float* __restrict__ W1,
    const float* __restrict__ b1, const float* __restrict__ W2,
    const float* __restrict__ b2)
{
    extern __shared__ char smc[];
    float* fl   = (float*)smc;
    float* W1s  = fl;               // 384
    float* W2s  = W1s + 384;        // 4096
    float* b1s  = W2s + 4096;       // 64
    float* b2s  = b1s + 64;         // 64
    float* S1   = b2s + 64;         // 64
    float* SH   = S1 + 64;          // 64
    float* xsum = SH + 64;          // 8
    float* part = xsum + 8;         // 256
    float* xs   = part + 256;       // 1248
    float* cjs  = xs + 1248;        // 64
    float* a2s  = cjs + 64;         // 64
    char*  A2h  = smc + G_AHI;
    char*  A2l  = smc + G_ALO;
    char*  B2h  = smc + G_BHI;
    char*  B2l  = smc + G_BLO;

    const int b = blockIdx.y;
    const int tid = threadIdx.x;
    const int lane = tid & 31;
    const float inv = 1.0f / 208.0f;

    for (int i = tid; i < 384;  i += 256) W1s[i] = W1[i];
    for (int i = tid; i < 4096; i += 256) W2s[i] = W2[i];
    for (int i = tid; i < 4096; i += 256) {
        int n = i >> 6, k = i & 63;
        unsigned short hh, ll;
        bf16split(W2[k * 64 + n], hh, ll);
        uint32_t off = (uint32_t)n * AR2 + (uint32_t)k * 2u;
        *(unsigned short*)(B2h + off) = hh;
        *(unsigned short*)(B2l + off) = ll;
    }
    if (tid < 64) { b1s[tid] = b1[tid]; b2s[tid] = b2[tid]; }

    for (int ti = 0; ti < 4; ++ti) {
        const int t = blockIdx.x * 4 + ti;
        {
            const float* xb = x + (size_t)b * (Nn * Tn * Fin) + t * Fin;
            for (int i = tid; i < Nn * Fin; i += 256) {
                int n = i / 6, f = i - n * 6;
                xs[i] = xb[n * (Tn * Fin) + f];
            }
        }
        __syncthreads();

        if (tid < 48) {
            int f = tid % 6, q = tid / 6;
            float s = 0.f;
            for (int n = q; n < Nn; n += 8) s += xs[n * 6 + f];
            part[tid] = s;
        }
        __syncthreads();
        if (tid < 6) {
            float s = 0.f;
            #pragma unroll
            for (int q = 0; q < 8; ++q) s += part[q * 6 + tid];
            xsum[tid] = s;
        }
        __syncthreads();
        if (tid < 64) {
            float s = 0.f;
            #pragma unroll
            for (int f = 0; f < 6; ++f) s += xsum[f] * W1s[f * 64 + tid];
            S1[tid] = s;
            cjs[tid] = fmaf(s, inv, b1s[tid]);
        }
        __syncthreads();

        if (tid < 208) {
            const int n = tid;
            float xr[6];
            #pragma unroll
            for (int f = 0; f < 6; ++f) xr[f] = (n < 207) ? xs[n * 6 + f] : 0.f;
            char* arh = A2h + (uint32_t)n * AR2;
            char* arl = A2l + (uint32_t)n * AR2;
            const int o = (lane >> 3) & 3;
            for (int s = 0; s < 32; ++s) {
                int wd = (o + s) & 31;
                int j = wd * 2;
                float v0 = xr[0] * W1s[j]       + xr[1] * W1s[64 + j]
                         + xr[2] * W1s[128 + j] + xr[3] * W1s[192 + j]
                         + xr[4] * W1s[256 + j] + xr[5] * W1s[320 + j];
                float v1 = xr[0] * W1s[j + 1]   + xr[1] * W1s[64 + j + 1]
                         + xr[2] * W1s[128 + j + 1] + xr[3] * W1s[192 + j + 1]
                         + xr[4] * W1s[256 + j + 1] + xr[5] * W1s[320 + j + 1];
                v0 = fmaxf(fmaf(v0, inv, cjs[j]), 0.f);
                v1 = fmaxf(fmaf(v1, inv, cjs[j + 1]), 0.f);
                unsigned short h0, l0, h1v, l1;
                bf16split(v0, h0, l0);
                bf16split(v1, h1v, l1);
                *(uint32_t*)(arh + j * 2) = (uint32_t)h0 | ((uint32_t)h1v << 16);
                *(uint32_t*)(arl + j * 2) = (uint32_t)l0 | ((uint32_t)l1 << 16);
            }
        }
        __syncthreads();

        {
            int j = tid & 63, q = tid >> 6;
            float s = 0.f;
            for (int n = q; n < 207; n += 4) {
                uint32_t hh = *(const unsigned short*)(A2h + (uint32_t)n * AR2 + j * 2);
                uint32_t ll = *(const unsigned short*)(A2l + (uint32_t)n * AR2 + j * 2);
                s += bf16bits2f(hh) + bf16bits2f(ll);
            }
            part[q * 64 + j] = s;
        }
        __syncthreads();
        if (tid < 64) SH[tid] = part[tid] + part[64 + tid] + part[128 + tid] + part[192 + tid];
        __syncthreads();
        if (tid < 64) {
            float s = 0.f;
            #pragma unroll 8
            for (int k = 0; k < 64; ++k) s += SH[k] * W2s[k * 64 + tid];
            a2s[tid] = fmaf(s, inv, b2s[tid]);
        }
        __syncthreads();

        {
            const int w = tid >> 5;
            const uint32_t aH = smem_u32(A2h), aL = smem_u32(A2l);
            const uint32_t bH = smem_u32(B2h), bL = smem_u32(B2l);
            const int ai = lane >> 3, arw = lane & 7;
            const int bl = lane & 15;
            const uint32_t bRowPart = (uint32_t)(bl & 7) * AR2 + (uint32_t)(((bl >> 3) & 1) << 4);

            #pragma unroll
            for (int rep = 0; rep < 2; ++rep) {
                const int mt = w + rep * 8;
                if (mt >= 13) break;
                float C[8][4];
                #pragma unroll
                for (int i = 0; i < 8; ++i)
                    #pragma unroll
                    for (int jj = 0; jj < 4; ++jj) C[i][jj] = 0.f;

                #pragma unroll
                for (int ks = 0; ks < 4; ++ks) {
                    const uint32_t kb = (uint32_t)ks * 32u;
                    uint32_t Ah[4], Al[4];
                    uint32_t ro = (uint32_t)(mt * 16 + ((ai & 1) << 3) + arw) * AR2
                                + (uint32_t)((ai >> 1) << 4) + kb;
                    LDSM4(Ah, aH + ro);
                    LDSM4(Al, aL + ro);
                    #pragma unroll
                    for (int nt = 0; nt < 8; ++nt) {
                        uint32_t rb = (uint32_t)(nt * 8) * AR2 + bRowPart + kb;
                        uint32_t Bh[2], Bl2[2];
                        LDSM2(Bh, bH + rb);
                        LDSM2(Bl2, bL + rb);
                        MMA16816(C[nt], Ah, Bh);
                        MMA16816(C[nt], Al, Bh);
                        MMA16816(C[nt], Ah, Bl2);
                    }
                }

                #pragma unroll
                for (int nt = 0; nt < 8; ++nt) {
                    const int j = nt * 8 + 2 * (lane & 3);
                    const float a0 = a2s[j], a1 = a2s[j + 1];
                    const int r0 = mt * 16 + (lane >> 2);
                    const int r1 = r0 + 8;
                    if (r0 < Nn) {
                        float2 o;
                        o.x = fmaxf(fmaf(C[nt][0], inv, a0), 0.f);
                        o.y = fmaxf(fmaf(C[nt][1], inv, a1), 0.f);
                        *(float2*)&g_h2[((size_t)(b * Nn + r0) * Tn + t) * Hd + j] = o;
                    }
                    if (r1 < Nn) {
                        float2 o;
                        o.x = fmaxf(fmaf(C[nt][2], inv, a0), 0.f);
                        o.y = fmaxf(fmaf(C[nt][3], inv, a1), 0.f);
                        *(float2*)&g_h2[((size_t)(b * Nn + r1) * Tn + t) * Hd + j] = o;
                    }
                }
            }
        }
        __syncthreads();   // protect xs/A2 for next timestep
    }
}

// =====================================================================
// Kernel 2: HMMA LSTM + FC.  138 CTAs x 384 threads (12 warps).
// PHASE-SKEW: odd warps process gate-phases in order (1,0) so their
// k-loop overlaps even warps' epilogue — tensor and MUFU co-resident.
// fp32 gates; double-buffered swizzled A; one sync/step; reg-prefetch x.
// =====================================================================
#define LNB  138
#define LNT  384
#define MROW 96
#define ABUF 49152            // one A buffer: hi 24576 + lo 24576
#define O_B_HI  98304         // 256 rows * 256B
#define O_B_LO  163840
#define O_BIAS  229376        // 256*4, [u*4+g], g==2 full else 0.5*b
#define O_WFC   230400        // 64*4
#define O_FCP   230656        // 96*4
#define LSMEM   231040

__device__ __forceinline__ uint32_t aswz(int row, int c16) {
    return (uint32_t)row * 256u
         + (uint32_t)((((c16) ^ (row & 7)) & 7) | ((c16) & 8)) * 16u;
}

// load x_t for this thread's (row, 16-col slice) into 4 float4 regs
__device__ __forceinline__ void load_x(float4* px, int tid, int blk, int t) {
    const int row = tid >> 2, cq = tid & 3;
    const float* gp = g_h2 + ((size_t)(blk * MROW + row) * Tn + t) * Hd + cq * 16;
    px[0] = ((const float4*)gp)[0];
    px[1] = ((const float4*)gp)[1];
    px[2] = ((const float4*)gp)[2];
    px[3] = ((const float4*)gp)[3];
}
// convert + store prefetched x into buffer cols 0..63
__device__ __forceinline__ void store_x(char* Dh, char* Dl, const float4* px, int tid) {
    const int row = tid >> 2, cq = tid & 3;
    float f[16] = { px[0].x, px[0].y, px[0].z, px[0].w,
                    px[1].x, px[1].y, px[1].z, px[1].w,
                    px[2].x, px[2].y, px[2].z, px[2].w,
                    px[3].x, px[3].y, px[3].z, px[3].w };
    unsigned short hh[16], ll[16];
    #pragma unroll
    for (int e = 0; e < 16; ++e) bf16split(f[e], hh[e], ll[e]);
    uint4 H0 = make_uint4((uint32_t)hh[0] | ((uint32_t)hh[1] << 16), (uint32_t)hh[2] | ((uint32_t)hh[3] << 16),
                          (uint32_t)hh[4] | ((uint32_t)hh[5] << 16), (uint32_t)hh[6] | ((uint32_t)hh[7] << 16));
    uint4 H1 = make_uint4((uint32_t)hh[8] | ((uint32_t)hh[9] << 16), (uint32_t)hh[10] | ((uint32_t)hh[11] << 16),
                          (uint32_t)hh[12] | ((uint32_t)hh[13] << 16), (uint32_t)hh[14] | ((uint32_t)hh[15] << 16));
    uint4 L0 = make_uint4((uint32_t)ll[0] | ((uint32_t)ll[1] << 16), (uint32_t)ll[2] | ((uint32_t)ll[3] << 16),
                          (uint32_t)ll[4] | ((uint32_t)ll[5] << 16), (uint32_t)ll[6] | ((uint32_t)ll[7] << 16));
    uint4 L1 = make_uint4((uint32_t)ll[8] | ((uint32_t)ll[9] << 16), (uint32_t)ll[10] | ((uint32_t)ll[11] << 16),
                          (uint32_t)ll[12] | ((uint32_t)ll[13] << 16), (uint32_t)ll[14] | ((uint32_t)ll[15] << 16));
    const uint32_t a0 = aswz(row, cq * 2);
    const uint32_t a1 = aswz(row, cq * 2 + 1);
    *(uint4*)(Dh + a0) = H0;
    *(uint4*)(Dh + a1) = H1;
    *(uint4*)(Dl + a0) = L0;
    *(uint4*)(Dl + a1) = L1;
}

__global__ void __launch_bounds__(LNT, 1) lstm_kernel(
    const float* __restrict__ Wih, const float* __restrict__ Whh,
    const float* __restrict__ bih, const float* __restrict__ bhh,
    const float* __restrict__ Wfc, const float* __restrict__ bfc,
    float* __restrict__ out)
{
    extern __shared__ char smc[];
    char*  Bhi   = smc + O_B_HI;
    char*  Blo   = smc + O_B_LO;
    float* bias2 = (float*)(smc + O_BIAS);
    float* wfcs  = (float*)(smc + O_WFC);
    float* fcp   = (float*)(smc + O_FCP);

    const int tid = threadIdx.x;

    // ---- stage weights B[n][k], n = g*64+u, swizzled 256B rows ----
    for (int i = tid; i < 256 * 128; i += LNT) {
        int n = i >> 7, k = i & 127;
        float v = (k < 64) ? Wih[n * 64 + k] : Whh[n * 64 + (k - 64)];
        unsigned short hh, ll;
        bf16split(v, hh, ll);
        uint32_t addr = aswz(n, k >> 3) + (uint32_t)((k * 2) & 15);
        *(unsigned short*)(Bhi + addr) = hh;
        *(unsigned short*)(Blo + addr) = ll;
    }
    // zero both A buffers (h0 = 0)
    for (int i = tid; i < (2 * ABUF) / 4; i += LNT) ((uint32_t*)smc)[i] = 0u;
    for (int i = tid; i < 256; i += LNT) {
        int u = i >> 2, g = i & 3;
        float b = bih[g * 64 + u] + bhh[g * 64 + u];
        bias2[i] = (g == 2) ? b : 0.5f * b;
    }
    if (tid < 64) wfcs[tid] = Wfc[tid];
    if (tid < MROW) fcp[tid] = 0.f;
    __syncthreads();

    const int w = tid >> 5, lane = tid & 31;
    const int mp = w % 3;        // 32-row M-pair: rows 32mp..+31
    const int nq = w / 3;        // 0..3: 8-unit slice per phase
    const int pfirst = w & 1;    // phase-skew: odd warps start with phase 1

    const uint32_t sb = smem_u32(smc);
    const uint32_t bH = sb + O_B_HI, bL = sb + O_B_LO;

    const int ai  = lane >> 3;
    const int arw = lane & 7;
    const int aCsel = ai >> 1;
    const uint32_t aBase0 = (uint32_t)(32 * mp + ((ai & 1) << 3) + arw) * 256u;
    const uint32_t aBase1 = aBase0 + 16u * 256u;
    const int bl  = lane & 15;
    const int bCsel = (bl >> 3) & 1;
    const uint32_t bBase = (uint32_t)((nq * 8 + (bl & 7)) * 256);

    float cst[16];
    #pragma unroll
    for (int i = 0; i < 16; ++i) cst[i] = 0.f;

    {
        float4 px0[4];
        load_x(px0, tid, blockIdx.x, 0);
        store_x(smc, smc + 24576, px0, tid);
    }
    __syncthreads();

    for (int t = 0; t < Tn; ++t) {
        const int rbuf = t & 1, wbuf = rbuf ^ 1;
        const uint32_t rdHi = sb + rbuf * ABUF, rdLo = rdHi + 24576;
        const bool last = (t == Tn - 1);

        // prefetch x_{t+1} NOW — LDG latency hides under the k-loops
        float4 px[4];
        if (t + 1 < Tn) load_x(px, tid, blockIdx.x, t + 1);

        char* WH = smc + wbuf * ABUF;
        char* WL = WH + 24576;

        #pragma unroll
        for (int pp = 0; pp < 2; ++pp) {
            const int p = pp ^ pfirst;      // phase-skew
            float C[2][4][4];
            #pragma unroll
            for (int m = 0; m < 2; ++m)
                #pragma unroll
                for (int g = 0; g < 4; ++g)
                    #pragma unroll
                    for (int jj = 0; jj < 4; ++jj) C[m][g][jj] = 0.f;

            #pragma unroll
            for (int ks = 0; ks < 8; ++ks) {
                const int ca = ks * 2 + aCsel;
                const uint32_t swa = (uint32_t)((((ca ^ arw) & 7) | (ca & 8)) << 4);
                const int cb = ks * 2 + bCsel;
                const uint32_t swb = (uint32_t)((((cb ^ (bl & 7)) & 7) | (cb & 8)) << 4);
                uint32_t Ah[2][4], Al[2][4];
                LDSM4(Ah[0], rdHi + aBase0 + swa);
                LDSM4(Al[0], rdLo + aBase0 + swa);
                LDSM4(Ah[1], rdHi + aBase1 + swa);
                LDSM4(Al[1], rdLo + aBase1 + swa);
                #pragma unroll
                for (int g = 0; g < 4; ++g) {
                    const uint32_t bo = bBase + (uint32_t)(g * 16384 + p * 8192) + swb;
                    uint32_t Bh[2], Bl2[2];
                    LDSM2(Bh, bH + bo);
                    MMA16816(C[0][g], Ah[0], Bh);
                    MMA16816(C[1][g], Ah[1], Bh);
                    MMA16816(C[0][g], Al[0], Bh);
                    MMA16816(C[1][g], Al[1], Bh);
                    LDSM2(Bl2, bL + bo);
                    MMA16816(C[0][g], Ah[0], Bl2);
                    MMA16816(C[1][g], Ah[1], Bl2);
                }
            }

            // fp32 epilogue for phase p: write h_t into the OTHER buffer
            const int c16 = 8 + p * 4 + nq;
            #pragma unroll
            for (int m = 0; m < 2; ++m)
                #pragma unroll
                for (int rh = 0; rh < 2; ++rh) {
                    const int row = 32 * mp + 16 * m + 8 * rh + (lane >> 2);
                    const uint32_t off = (uint32_t)row * 256u
                        + (uint32_t)((((c16 ^ (row & 7)) & 7) | 8) << 4)
                        + (uint32_t)(4 * (lane & 3));
                    uint32_t hiw = 0u, low = 0u;
                    #pragma unroll
                    for (int e = 0; e < 2; ++e) {
                        const int u = p * 32 + nq * 8 + 2 * (lane & 3) + e;
                        const float4 bb = *(const float4*)(bias2 + 4 * u);
                        const int idx4 = rh * 2 + e;
                        const float gi = C[m][0][idx4];
                        const float gf = C[m][1][idx4];
                        const float gg = C[m][2][idx4];
                        const float go = C[m][3][idx4];
                        const float ig = sigm2(gi, bb.x);
                        const float fg = sigm2(gf, bb.y);
                        const float g_ = tanhm(gg + bb.z);
                        const float og = sigm2(go, bb.w);
                        const int ci = ((p * 2 + m) * 2 + rh) * 2 + e;
                        const float cn = fmaf(fg, cst[ci], ig * g_);
                        cst[ci] = cn;
                        const float hv = og * tanhm(cn);
                        unsigned short hh, ll;
                        bf16split(hv, hh, ll);
                        hiw |= ((uint32_t)hh) << (16 * e);
                        low |= ((uint32_t)ll) << (16 * e);
                        if (last) atomicAdd(&fcp[row], hv * wfcs[u]);
                    }
                    *(uint32_t*)(WH + off) = hiw;
                    *(uint32_t*)(WL + off) = low;
                }
        }

        if (t + 1 < Tn) store_x(WH, WL, px, tid);
        __syncthreads();   // single barrier per step
    }

    if (tid < MROW) out[blockIdx.x * MROW + tid] = fcp[tid] + bfc[0];
}

// =====================================================================
extern "C" void kernel_launch(void* const* d_in, const int* in_sizes, int n_in,
                              void* d_out, int out_size)
{
    const float* x   = (const float*)d_in[0];
    // d_in[1], d_in[2] = N1, N2: structurally irrelevant (sigmoid > 0 everywhere)
    const float* W1  = (const float*)d_in[3];
    const float* b1  = (const float*)d_in[4];
    const float* W2  = (const float*)d_in[5];
    const float* b2  = (const float*)d_in[6];
    const float* Wih = (const float*)d_in[7];
    const float* Whh = (const float*)d_in[8];
    const float* bih = (const float*)d_in[9];
    const float* bhh = (const float*)d_in[10];
    const float* Wfc = (const float*)d_in[11];
    const float* bfc = (const float*)d_in[12];
    float* out = (float*)d_out;

    cudaFuncSetAttribute(gcn_kernel,  cudaFuncAttributeMaxDynamicSharedMemorySize, G_SMEM);
    cudaFuncSetAttribute(lstm_kernel, cudaFuncAttributeMaxDynamicSharedMemorySize, LSMEM);

    gcn_kernel<<<dim3(Tn / 4, Bn), 256, G_SMEM>>>(x, W1, b1, W2, b2);
    lstm_kernel<<<LNB, LNT, LSMEM>>>(Wih, Whh, bih, bhh, Wfc, bfc, out);
}

// round 14
// speedup vs baseline: 1.0326x; 1.0326x over previous
#include <cuda_runtime.h>
#include <cuda_bf16.h>
#include <cstdint>

#define Bn   64
#define Nn   207
#define Tn   48
#define Fin  6
#define Hd   64
#define NSEQ (Bn * Nn)        // 13248

// scratch: GCN output / LSTM input, [seq][t][Hd]
__device__ float g_h2[(size_t)NSEQ * Tn * Hd];   // 162.8 MB

__device__ __forceinline__ float tanhm(float x) {
    float r; asm("tanh.approx.f32 %0, %1;" : "=f"(r) : "f"(x)); return r;
}
// sigmoid(x + b) with bh = 0.5*b precomputed
__device__ __forceinline__ float sigm2(float x, float bh) {
    return fmaf(tanhm(fmaf(x, 0.5f, bh)), 0.5f, 0.5f);
}
__device__ __forceinline__ uint32_t smem_u32(const void* p) {
    uint32_t a;
    asm("{ .reg .u64 t; cvta.to.shared.u64 t, %1; cvt.u32.u64 %0, t; }" : "=r"(a) : "l"(p));
    return a;
}

#define LDSM4(R, a) asm volatile("ldmatrix.sync.aligned.m8n8.x4.shared.b16 {%0,%1,%2,%3}, [%4];" \
    : "=r"((R)[0]), "=r"((R)[1]), "=r"((R)[2]), "=r"((R)[3]) : "r"(a))
#define LDSM2(R, a) asm volatile("ldmatrix.sync.aligned.m8n8.x2.shared.b16 {%0,%1}, [%2];" \
    : "=r"((R)[0]), "=r"((R)[1]) : "r"(a))
#define MMA16816(C, A, B) asm volatile( \
    "mma.sync.aligned.m16n8k16.row.col.f32.bf16.bf16.f32 " \
    "{%0,%1,%2,%3}, {%4,%5,%6,%7}, {%8,%9}, {%0,%1,%2,%3};" \
    : "+f"((C)[0]), "+f"((C)[1]), "+f"((C)[2]), "+f"((C)[3]) \
    : "r"((A)[0]), "r"((A)[1]), "r"((A)[2]), "r"((A)[3]), "r"((B)[0]), "r"((B)[1]))

__device__ __forceinline__ void bf16split(float v, unsigned short& h, unsigned short& l) {
    __nv_bfloat16 hb = __float2bfloat16(v);
    h = __bfloat16_as_ushort(hb);
    l = __bfloat16_as_ushort(__float2bfloat16(v - __bfloat162float(hb)));
}
__device__ __forceinline__ float bf16bits2f(uint32_t u) {
    return __uint_as_float(u << 16);
}

// =====================================================================
// Kernel 1: fused 2-layer GCN, z2 via HMMA.  grid (12, Bn), 512 thr,
// 4 timesteps per block.  A_hat[m][n] = (1 + (m==n)) / 208
// 512 threads: wider staging/reductions, single balanced MMA pass.
// =====================================================================
#define GTHR 512
#define AR2 144
// float region: W1s 384|W2s 4096|b1s 64|b2s 64|S1 64|SH 64|xsum 8|
//               part 512|xs 1248|cjs 64|a2s 64  = 6632 floats
#define G_AHI   26624    // 208*144 = 29952
#define G_ALO   56576
#define G_BHI   86528    // 64*144 = 9216
#define G_BLO   95744
#define G_SMEM  104960

__global__ void __launch_bounds__(GTHR, 2) gcn_kernel(
    const float* __restrict__ x,  const float* __restrict__ W1,
    const float* __restrict__ b1, const float* __restrict__ W2,
    const float* __restrict__ b2)
{
    extern __shared__ char smc[];
    float* fl   = (float*)smc;
    float* W1s  = fl;               // 384
    float* W2s  = W1s + 384;        // 4096
    float* b1s  = W2s + 4096;       // 64
    float* b2s  = b1s + 64;         // 64
    float* S1   = b2s + 64;         // 64
    float* SH   = S1 + 64;          // 64
    float* xsum = SH + 64;          // 8
    float* part = xsum + 8;         // 512
    float* xs   = part + 512;       // 1248
    float* cjs  = xs + 1248;        // 64
    float* a2s  = cjs + 64;         // 64
    char*  A2h  = smc + G_AHI;
    char*  A2l  = smc + G_ALO;
    char*  B2h  = smc + G_BHI;
    char*  B2l  = smc + G_BLO;

    const int b = blockIdx.y;
    const int tid = threadIdx.x;
    const int lane = tid & 31;
    const float inv = 1.0f / 208.0f;

    for (int i = tid; i < 384;  i += GTHR) W1s[i] = W1[i];
    for (int i = tid; i < 4096; i += GTHR) W2s[i] = W2[i];
    for (int i = tid; i < 4096; i += GTHR) {
        int n = i >> 6, k = i & 63;
        unsigned short hh, ll;
        bf16split(W2[k * 64 + n], hh, ll);
        uint32_t off = (uint32_t)n * AR2 + (uint32_t)k * 2u;
        *(unsigned short*)(B2h + off) = hh;
        *(unsigned short*)(B2l + off) = ll;
    }
    if (tid < 64) { b1s[tid] = b1[tid]; b2s[tid] = b2[tid]; }

    for (int ti = 0; ti < 4; ++ti) {
        const int t = blockIdx.x * 4 + ti;
        {
            const float* xb = x + (size_t)b * (Nn * Tn * Fin) + t * Fin;
            for (int i = tid; i < Nn * Fin; i += GTHR) {
                int n = i / 6, f = i - n * 6;
                xs[i] = xb[n * (Tn * Fin) + f];
            }
        }
        __syncthreads();

        // xsum[f] = sum_n x[n][f]
        if (tid < 48) {
            int f = tid % 6, q = tid / 6;
            float s = 0.f;
            for (int n = q; n < Nn; n += 8) s += xs[n * 6 + f];
            part[tid] = s;
        }
        __syncthreads();
        if (tid < 6) {
            float s = 0.f;
            #pragma unroll
            for (int q = 0; q < 8; ++q) s += part[q * 6 + tid];
            xsum[tid] = s;
        }
        __syncthreads();
        if (tid < 64) {
            float s = 0.f;
            #pragma unroll
            for (int f = 0; f < 6; ++f) s += xsum[f] * W1s[f * 64 + tid];
            S1[tid] = s;
            cjs[tid] = fmaf(s, inv, b1s[tid]);
        }
        __syncthreads();

        // h1 -> A (bf16 hi/lo): 416 threads, each (n, half) does 16 j-pairs
        if (tid < 416) {
            const int n = tid >> 1, half = tid & 1;
            float xr[6];
            #pragma unroll
            for (int f = 0; f < 6; ++f) xr[f] = (n < 207) ? xs[n * 6 + f] : 0.f;
            char* arh = A2h + (uint32_t)n * AR2;
            char* arl = A2l + (uint32_t)n * AR2;
            const int o = (lane >> 3) & 3;
            for (int s = 0; s < 16; ++s) {
                int wd = half * 16 + ((o + s) & 15);
                int j = wd * 2;
                float v0 = xr[0] * W1s[j]       + xr[1] * W1s[64 + j]
                         + xr[2] * W1s[128 + j] + xr[3] * W1s[192 + j]
                         + xr[4] * W1s[256 + j] + xr[5] * W1s[320 + j];
                float v1 = xr[0] * W1s[j + 1]   + xr[1] * W1s[64 + j + 1]
                         + xr[2] * W1s[128 + j + 1] + xr[3] * W1s[192 + j + 1]
                         + xr[4] * W1s[256 + j + 1] + xr[5] * W1s[320 + j + 1];
                v0 = fmaxf(fmaf(v0, inv, cjs[j]), 0.f);
                v1 = fmaxf(fmaf(v1, inv, cjs[j + 1]), 0.f);
                unsigned short h0, l0, h1v, l1;
                bf16split(v0, h0, l0);
                bf16split(v1, h1v, l1);
                *(uint32_t*)(arh + j * 2) = (uint32_t)h0 | ((uint32_t)h1v << 16);
                *(uint32_t*)(arl + j * 2) = (uint32_t)l0 | ((uint32_t)l1 << 16);
            }
        }
        __syncthreads();

        // SH[j] = sum_n h1'[n][j] (8-way partials over 512 threads)
        {
            int j = tid & 63, q = tid >> 6;
            float s = 0.f;
            for (int n = q; n < 207; n += 8) {
                uint32_t hh = *(const unsigned short*)(A2h + (uint32_t)n * AR2 + j * 2);
                uint32_t ll = *(const unsigned short*)(A2l + (uint32_t)n * AR2 + j * 2);
                s += bf16bits2f(hh) + bf16bits2f(ll);
            }
            part[q * 64 + j] = s;
        }
        __syncthreads();
        if (tid < 64) {
            float s = 0.f;
            #pragma unroll
            for (int q = 0; q < 8; ++q) s += part[q * 64 + tid];
            SH[tid] = s;
        }
        __syncthreads();
        if (tid < 64) {
            float s = 0.f;
            #pragma unroll 8
            for (int k = 0; k < 64; ++k) s += SH[k] * W2s[k * 64 + tid];
            a2s[tid] = fmaf(s, inv, b2s[tid]);
        }
        __syncthreads();

        // z2 via HMMA: single balanced pass, warps 0..12 take one M-tile
        {
            const int w = tid >> 5;
            if (w < 13) {
                const int mt = w;
                const uint32_t aH = smem_u32(A2h), aL = smem_u32(A2l);
                const uint32_t bH = smem_u32(B2h), bL = smem_u32(B2l);
                const int ai = lane >> 3, arw = lane & 7;
                const int bl = lane & 15;
                const uint32_t bRowPart = (uint32_t)(bl & 7) * AR2
                                        + (uint32_t)(((bl >> 3) & 1) << 4);
                float C[8][4];
                #pragma unroll
                for (int i = 0; i < 8; ++i)
                    #pragma unroll
                    for (int jj = 0; jj < 4; ++jj) C[i][jj] = 0.f;

                #pragma unroll
                for (int ks = 0; ks < 4; ++ks) {
                    const uint32_t kb = (uint32_t)ks * 32u;
                    uint32_t Ah[4], Al[4];
                    uint32_t ro = (uint32_t)(mt * 16 + ((ai & 1) << 3) + arw) * AR2
                                + (uint32_t)((ai >> 1) << 4) + kb;
                    LDSM4(Ah, aH + ro);
                    LDSM4(Al, aL + ro);
                    #pragma unroll
                    for (int nt = 0; nt < 8; ++nt) {
                        uint32_t rb = (uint32_t)(nt * 8) * AR2 + bRowPart + kb;
                        uint32_t Bh[2], Bl2[2];
                        LDSM2(Bh, bH + rb);
                        LDSM2(Bl2, bL + rb);
                        MMA16816(C[nt], Ah, Bh);
                        MMA16816(C[nt], Al, Bh);
                        MMA16816(C[nt], Ah, Bl2);
                    }
                }

                #pragma unroll
                for (int nt = 0; nt < 8; ++nt) {
                    const int j = nt * 8 + 2 * (lane & 3);
                    const float a0 = a2s[j], a1 = a2s[j + 1];
                    const int r0 = mt * 16 + (lane >> 2);
                    const int r1 = r0 + 8;
                    if (r0 < Nn) {
                        float2 o;
                        o.x = fmaxf(fmaf(C[nt][0], inv, a0), 0.f);
                        o.y = fmaxf(fmaf(C[nt][1], inv, a1), 0.f);
                        *(float2*)&g_h2[((size_t)(b * Nn + r0) * Tn + t) * Hd + j] = o;
                    }
                    if (r1 < Nn) {
                        float2 o;
                        o.x = fmaxf(fmaf(C[nt][2], inv, a0), 0.f);
                        o.y = fmaxf(fmaf(C[nt][3], inv, a1), 0.f);
                        *(float2*)&g_h2[((size_t)(b * Nn + r1) * Tn + t) * Hd + j] = o;
                    }
                }
            }
        }
        __syncthreads();   // protect xs/A2 for next timestep
    }
}

// =====================================================================
// Kernel 2: HMMA LSTM + FC (byte-exact R12 — proven 369 us, 6.1e-6).
// 138 CTAs x 384 threads; warp owns 32 rows x 8-unit slice; fp32 gates;
// double-buffered swizzled A; one sync/step; reg-prefetch x.
// =====================================================================
#define LNB  138
#define LNT  384
#define MROW 96
#define ABUF 49152
#define O_B_HI  98304
#define O_B_LO  163840
#define O_BIAS  229376
#define O_WFC   230400
#define O_FCP   230656
#define LSMEM   231040

__device__ __forceinline__ uint32_t aswz(int row, int c16) {
    return (uint32_t)row * 256u
         + (uint32_t)((((c16) ^ (row & 7)) & 7) | ((c16) & 8)) * 16u;
}

__device__ __forceinline__ void load_x(float4* px, int tid, int blk, int t) {
    const int row = tid >> 2, cq = tid & 3;
    const float* gp = g_h2 + ((size_t)(blk * MROW + row) * Tn + t) * Hd + cq * 16;
    px[0] = ((const float4*)gp)[0];
    px[1] = ((const float4*)gp)[1];
    px[2] = ((const float4*)gp)[2];
    px[3] = ((const float4*)gp)[3];
}
__device__ __forceinline__ void store_x(char* Dh, char* Dl, const float4* px, int tid) {
    const int row = tid >> 2, cq = tid & 3;
    float f[16] = { px[0].x, px[0].y, px[0].z, px[0].w,
                    px[1].x, px[1].y, px[1].z, px[1].w,
                    px[2].x, px[2].y, px[2].z, px[2].w,
                    px[3].x, px[3].y, px[3].z, px[3].w };
    unsigned short hh[16], ll[16];
    #pragma unroll
    for (int e = 0; e < 16; ++e) bf16split(f[e], hh[e], ll[e]);
    uint4 H0 = make_uint4((uint32_t)hh[0] | ((uint32_t)hh[1] << 16), (uint32_t)hh[2] | ((uint32_t)hh[3] << 16),
                          (uint32_t)hh[4] | ((uint32_t)hh[5] << 16), (uint32_t)hh[6] | ((uint32_t)hh[7] << 16));
    uint4 H1 = make_uint4((uint32_t)hh[8] | ((uint32_t)hh[9] << 16), (uint32_t)hh[10] | ((uint32_t)hh[11] << 16),
                          (uint32_t)hh[12] | ((uint32_t)hh[13] << 16), (uint32_t)hh[14] | ((uint32_t)hh[15] << 16));
    uint4 L0 = make_uint4((uint32_t)ll[0] | ((uint32_t)ll[1] << 16), (uint32_t)ll[2] | ((uint32_t)ll[3] << 16),
                          (uint32_t)ll[4] | ((uint32_t)ll[5] << 16), (uint32_t)ll[6] | ((uint32_t)ll[7] << 16));
    uint4 L1 = make_uint4((uint32_t)ll[8] | ((uint32_t)ll[9] << 16), (uint32_t)ll[10] | ((uint32_t)ll[11] << 16),
                          (uint32_t)ll[12] | ((uint32_t)ll[13] << 16), (uint32_t)ll[14] | ((uint32_t)ll[15] << 16));
    const uint32_t a0 = aswz(row, cq * 2);
    const uint32_t a1 = aswz(row, cq * 2 + 1);
    *(uint4*)(Dh + a0) = H0;
    *(uint4*)(Dh + a1) = H1;
    *(uint4*)(Dl + a0) = L0;
    *(uint4*)(Dl + a1) = L1;
}

__global__ void __launch_bounds__(LNT, 1) lstm_kernel(
    const float* __restrict__ Wih, const float* __restrict__ Whh,
    const float* __restrict__ bih, const float* __restrict__ bhh,
    const float* __restrict__ Wfc, const float* __restrict__ bfc,
    float* __restrict__ out)
{
    extern __shared__ char smc[];
    char*  Bhi   = smc + O_B_HI;
    char*  Blo   = smc + O_B_LO;
    float* bias2 = (float*)(smc + O_BIAS);
    float* wfcs  = (float*)(smc + O_WFC);
    float* fcp   = (float*)(smc + O_FCP);

    const int tid = threadIdx.x;

    for (int i = tid; i < 256 * 128; i += LNT) {
        int n = i >> 7, k = i & 127;
        float v = (k < 64) ? Wih[n * 64 + k] : Whh[n * 64 + (k - 64)];
        unsigned short hh, ll;
        bf16split(v, hh, ll);
        uint32_t addr = aswz(n, k >> 3) + (uint32_t)((k * 2) & 15);
        *(unsigned short*)(Bhi + addr) = hh;
        *(unsigned short*)(Blo + addr) = ll;
    }
    for (int i = tid; i < (2 * ABUF) / 4; i += LNT) ((uint32_t*)smc)[i] = 0u;
    for (int i = tid; i < 256; i += LNT) {
        int u = i >> 2, g = i & 3;
        float b = bih[g * 64 + u] + bhh[g * 64 + u];
        bias2[i] = (g == 2) ? b : 0.5f * b;
    }
    if (tid < 64) wfcs[tid] = Wfc[tid];
    if (tid < MROW) fcp[tid] = 0.f;
    __syncthreads();

    const int w = tid >> 5, lane = tid & 31;
    const int mp = w % 3;
    const int nq = w / 3;

    const uint32_t sb = smem_u32(smc);
    const uint32_t bH = sb + O_B_HI, bL = sb + O_B_LO;

    const int ai  = lane >> 3;
    const int arw = lane & 7;
    const int aCsel = ai >> 1;
    const uint32_t aBase0 = (uint32_t)(32 * mp + ((ai & 1) << 3) + arw) * 256u;
    const uint32_t aBase1 = aBase0 + 16u * 256u;
    const int bl  = lane & 15;
    const int bCsel = (bl >> 3) & 1;
    const uint32_t bBase = (uint32_t)((nq * 8 + (bl & 7)) * 256);

    float cst[16];
    #pragma unroll
    for (int i = 0; i < 16; ++i) cst[i] = 0.f;

    {
        float4 px0[4];
        load_x(px0, tid, blockIdx.x, 0);
        store_x(smc, smc + 24576, px0, tid);
    }
    __syncthreads();

    for (int t = 0; t < Tn; ++t) {
        const int rbuf = t & 1, wbuf = rbuf ^ 1;
        const uint32_t rdHi = sb + rbuf * ABUF, rdLo = rdHi + 24576;
        const bool last = (t == Tn - 1);

        float4 px[4];
        if (t + 1 < Tn) load_x(px, tid, blockIdx.x, t + 1);

        char* WH = smc + wbuf * ABUF;
        char* WL = WH + 24576;

        #pragma unroll
        for (int p = 0; p < 2; ++p) {
            float C[2][4][4];
            #pragma unroll
            for (int m = 0; m < 2; ++m)
                #pragma unroll
                for (int g = 0; g < 4; ++g)
                    #pragma unroll
                    for (int jj = 0; jj < 4; ++jj) C[m][g][jj] = 0.f;

            #pragma unroll
            for (int ks = 0; ks < 8; ++ks) {
                const int ca = ks * 2 + aCsel;
                const uint32_t swa = (uint32_t)((((ca ^ arw) & 7) | (ca & 8)) << 4);
                const int cb = ks * 2 + bCsel;
                const uint32_t swb = (uint32_t)((((cb ^ (bl & 7)) & 7) | (cb & 8)) << 4);
                uint32_t Ah[2][4], Al[2][4];
                LDSM4(Ah[0], rdHi + aBase0 + swa);
                LDSM4(Al[0], rdLo + aBase0 + swa);
                LDSM4(Ah[1], rdHi + aBase1 + swa);
                LDSM4(Al[1], rdLo + aBase1 + swa);
                #pragma unroll
                for (int g = 0; g < 4; ++g) {
                    const uint32_t bo = bBase + (uint32_t)(g * 16384 + p * 8192) + swb;
                    uint32_t Bh[2], Bl2[2];
                    LDSM2(Bh, bH + bo);
                    MMA16816(C[0][g], Ah[0], Bh);
                    MMA16816(C[1][g], Ah[1], Bh);
                    MMA16816(C[0][g], Al[0], Bh);
                    MMA16816(C[1][g], Al[1], Bh);
                    LDSM2(Bl2, bL + bo);
                    MMA16816(C[0][g], Ah[0], Bl2);
                    MMA16816(C[1][g], Ah[1], Bl2);
                }
            }

            const int c16 = 8 + p * 4 + nq;
            #pragma unroll
            for (int m = 0; m < 2; ++m)
                #pragma unroll
                for (int rh = 0; rh < 2; ++rh) {
                    const int row = 32 * mp + 16 * m + 8 * rh + (lane >> 2);
                    const uint32_t off = (uint32_t)row * 256u
                        + (uint32_t)((((c16 ^ (row & 7)) & 7) | 8) << 4)
                        + (uint32_t)(4 * (lane & 3));
                    uint32_t hiw = 0u, low = 0u;
                    #pragma unroll
                    for (int e = 0; e < 2; ++e) {
                        const int u = p * 32 + nq * 8 + 2 * (lane & 3) + e;
                        const float4 bb = *(const float4*)(bias2 + 4 * u);
                        const int idx4 = rh * 2 + e;
                        const float gi = C[m][0][idx4];
                        const float gf = C[m][1][idx4];
                        const float gg = C[m][2][idx4];
                        const float go = C[m][3][idx4];
                        const float ig = sigm2(gi, bb.x);
                        const float fg = sigm2(gf, bb.y);
                        const float g_ = tanhm(gg + bb.z);
                        const float og = sigm2(go, bb.w);
                        const int ci = ((p * 2 + m) * 2 + rh) * 2 + e;
                        const float cn = fmaf(fg, cst[ci], ig * g_);
                        cst[ci] = cn;
                        const float hv = og * tanhm(cn);
                        unsigned short hh, ll;
                        bf16split(hv, hh, ll);
                        hiw |= ((uint32_t)hh) << (16 * e);
                        low |= ((uint32_t)ll) << (16 * e);
                        if (last) atomicAdd(&fcp[row], hv * wfcs[u]);
                    }
                    *(uint32_t*)(WH + off) = hiw;
                    *(uint32_t*)(WL + off) = low;
                }
        }

        if (t + 1 < Tn) store_x(WH, WL, px, tid);
        __syncthreads();
    }

    if (tid < MROW) out[blockIdx.x * MROW + tid] = fcp[tid] + bfc[0];
}

// =====================================================================
extern "C" void kernel_launch(void* const* d_in, const int* in_sizes, int n_in,
                              void* d_out, int out_size)
{
    const float* x   = (const float*)d_in[0];
    // d_in[1], d_in[2] = N1, N2: structurally irrelevant (sigmoid > 0 everywhere)
    const float* W1  = (const float*)d_in[3];
    const float* b1  = (const float*)d_in[4];
    const float* W2  = (const float*)d_in[5];
    const float* b2  = (const float*)d_in[6];
    const float* Wih = (const float*)d_in[7];
    const float* Whh = (const float*)d_in[8];
    const float* bih = (const float*)d_in[9];
    const float* bhh = (const float*)d_in[10];
    const float* Wfc = (const float*)d_in[11];
    const float* bfc = (const float*)d_in[12];
    float* out = (float*)d_out;

    cudaFuncSetAttribute(gcn_kernel,  cudaFuncAttributeMaxDynamicSharedMemorySize, G_SMEM);
    cudaFuncSetAttribute(lstm_kernel, cudaFuncAttributeMaxDynamicSharedMemorySize, LSMEM);

    gcn_kernel<<<dim3(Tn / 4, Bn), GTHR, G_SMEM>>>(x, W1, b1, W2, b2);
    lstm_kernel<<<LNB, LNT, LSMEM>>>(Wih, Whh, bih, bhh, Wfc, bfc, out);
}

// round 15
// speedup vs baseline: 1.5484x; 1.4995x over previous
#include <cuda_runtime.h>
#include <cuda_bf16.h>
#include <cstdint>

#define Bn   64
#define Nn   207
#define Tn   48
#define Fin  6
#define Hd   64
#define NSEQ (Bn * Nn)        // 13248

// scratch: GCN output / LSTM input, [seq][t][Hd]
__device__ float g_h2[(size_t)NSEQ * Tn * Hd];   // 162.8 MB

__device__ __forceinline__ float tanhm(float x) {
    float r; asm("tanh.approx.f32 %0, %1;" : "=f"(r) : "f"(x)); return r;
}
// sigmoid(x + b) with bh = 0.5*b precomputed
__device__ __forceinline__ float sigm2(float x, float bh) {
    return fmaf(tanhm(fmaf(x, 0.5f, bh)), 0.5f, 0.5f);
}
__device__ __forceinline__ uint32_t smem_u32(const void* p) {
    uint32_t a;
    asm("{ .reg .u64 t; cvta.to.shared.u64 t, %1; cvt.u32.u64 %0, t; }" : "=r"(a) : "l"(p));
    return a;
}

#define LDSM4(R, a) asm volatile("ldmatrix.sync.aligned.m8n8.x4.shared.b16 {%0,%1,%2,%3}, [%4];" \
    : "=r"((R)[0]), "=r"((R)[1]), "=r"((R)[2]), "=r"((R)[3]) : "r"(a))
#define LDSM2(R, a) asm volatile("ldmatrix.sync.aligned.m8n8.x2.shared.b16 {%0,%1}, [%2];" \
    : "=r"((R)[0]), "=r"((R)[1]) : "r"(a))
#define MMA16816(C, A, B) asm volatile( \
    "mma.sync.aligned.m16n8k16.row.col.f32.bf16.bf16.f32 " \
    "{%0,%1,%2,%3}, {%4,%5,%6,%7}, {%8,%9}, {%0,%1,%2,%3};" \
    : "+f"((C)[0]), "+f"((C)[1]), "+f"((C)[2]), "+f"((C)[3]) \
    : "r"((A)[0]), "r"((A)[1]), "r"((A)[2]), "r"((A)[3]), "r"((B)[0]), "r"((B)[1]))

__device__ __forceinline__ void bf16split(float v, unsigned short& h, unsigned short& l) {
    __nv_bfloat16 hb = __float2bfloat16(v);
    h = __bfloat16_as_ushort(hb);
    l = __bfloat16_as_ushort(__float2bfloat16(v - __bfloat162float(hb)));
}
__device__ __forceinline__ float bf16bits2f(uint32_t u) {
    return __uint_as_float(u << 16);
}

// =====================================================================
// Kernel 1: fused 2-layer GCN, z2 via HMMA.  grid (12, Bn), 256 thr,
// 4 timesteps per block.  A_hat[m][n] = (1 + (m==n)) / 208
// (proven R12 version)
// =====================================================================
#define AR2 144
#define G_AHI   25760
#define G_ALO   55712
#define G_BHI   85664
#define G_BLO   94880
#define G_SMEM  104096

__global__ void __launch_bounds__(256, 2) gcn_kernel(
    const float* __restrict__ x,  const float* __restrict__ W1,
    const float* __restrict__ b1, const float* __restrict__ W2,
    const float* __restrict__ b2)
{
    extern __shared__ char smc[];
    float* fl   = (float*)smc;
    float* W1s  = fl;               // 384
    float* W2s  = W1s + 384;        // 4096
    float* b1s  = W2s + 4096;       // 64
    float* b2s  = b1s + 64;         // 64
    float* S1   = b2s + 64;         // 64
    float* SH   = S1 + 64;          // 64
    float* xsum = SH + 64;          // 8
    float* part = xsum + 8;         // 256
    float* xs   = part + 256;       // 1248
    float* cjs  = xs + 1248;        // 64
    float* a2s  = cjs + 64;         // 64
    char*  A2h  = smc + G_AHI;
    char*  A2l  = smc + G_ALO;
    char*  B2h  = smc + G_BHI;
    char*  B2l  = smc + G_BLO;

    const int b = blockIdx.y;
    const int tid = threadIdx.x;
    const int lane = tid & 31;
    const float inv = 1.0f / 208.0f;

    for (int i = tid; i < 384;  i += 256) W1s[i] = W1[i];
    for (int i = tid; i < 4096; i += 256) W2s[i] = W2[i];
    for (int i = tid; i < 4096; i += 256) {
        int n = i >> 6, k = i & 63;
        unsigned short hh, ll;
        bf16split(W2[k * 64 + n], hh, ll);
        uint32_t off = (uint32_t)n * AR2 + (uint32_t)k * 2u;
        *(unsigned short*)(B2h + off) = hh;
        *(unsigned short*)(B2l + off) = ll;
    }
    if (tid < 64) { b1s[tid] = b1[tid]; b2s[tid] = b2[tid]; }

    for (int ti = 0; ti < 4; ++ti) {
        const int t = blockIdx.x * 4 + ti;
        {
            const float* xb = x + (size_t)b * (Nn * Tn * Fin) + t * Fin;
            for (int i = tid; i < Nn * Fin; i += 256) {
                int n = i / 6, f = i - n * 6;
                xs[i] = xb[n * (Tn * Fin) + f];
            }
        }
        __syncthreads();

        if (tid < 48) {
            int f = tid % 6, q = tid / 6;
            float s = 0.f;
            for (int n = q; n < Nn; n += 8) s += xs[n * 6 + f];
            part[tid] = s;
        }
        __syncthreads();
        if (tid < 6) {
            float s = 0.f;
            #pragma unroll
            for (int q = 0; q < 8; ++q) s += part[q * 6 + tid];
            xsum[tid] = s;
        }
        __syncthreads();
        if (tid < 64) {
            float s = 0.f;
            #pragma unroll
            for (int f = 0; f < 6; ++f) s += xsum[f] * W1s[f * 64 + tid];
            S1[tid] = s;
            cjs[tid] = fmaf(s, inv, b1s[tid]);
        }
        __syncthreads();

        if (tid < 208) {
            const int n = tid;
            float xr[6];
            #pragma unroll
            for (int f = 0; f < 6; ++f) xr[f] = (n < 207) ? xs[n * 6 + f] : 0.f;
            char* arh = A2h + (uint32_t)n * AR2;
            char* arl = A2l + (uint32_t)n * AR2;
            const int o = (lane >> 3) & 3;
            for (int s = 0; s < 32; ++s) {
                int wd = (o + s) & 31;
                int j = wd * 2;
                float v0 = xr[0] * W1s[j]       + xr[1] * W1s[64 + j]
                         + xr[2] * W1s[128 + j] + xr[3] * W1s[192 + j]
                         + xr[4] * W1s[256 + j] + xr[5] * W1s[320 + j];
                float v1 = xr[0] * W1s[j + 1]   + xr[1] * W1s[64 + j + 1]
                         + xr[2] * W1s[128 + j + 1] + xr[3] * W1s[192 + j + 1]
                         + xr[4] * W1s[256 + j + 1] + xr[5] * W1s[320 + j + 1];
                v0 = fmaxf(fmaf(v0, inv, cjs[j]), 0.f);
                v1 = fmaxf(fmaf(v1, inv, cjs[j + 1]), 0.f);
                unsigned short h0, l0, h1v, l1;
                bf16split(v0, h0, l0);
                bf16split(v1, h1v, l1);
                *(uint32_t*)(arh + j * 2) = (uint32_t)h0 | ((uint32_t)h1v << 16);
                *(uint32_t*)(arl + j * 2) = (uint32_t)l0 | ((uint32_t)l1 << 16);
            }
        }
        __syncthreads();

        {
            int j = tid & 63, q = tid >> 6;
            float s = 0.f;
            for (int n = q; n < 207; n += 4) {
                uint32_t hh = *(const unsigned short*)(A2h + (uint32_t)n * AR2 + j * 2);
                uint32_t ll = *(const unsigned short*)(A2l + (uint32_t)n * AR2 + j * 2);
                s += bf16bits2f(hh) + bf16bits2f(ll);
            }
            part[q * 64 + j] = s;
        }
        __syncthreads();
        if (tid < 64) SH[tid] = part[tid] + part[64 + tid] + part[128 + tid] + part[192 + tid];
        __syncthreads();
        if (tid < 64) {
            float s = 0.f;
            #pragma unroll 8
            for (int k = 0; k < 64; ++k) s += SH[k] * W2s[k * 64 + tid];
            a2s[tid] = fmaf(s, inv, b2s[tid]);
        }
        __syncthreads();

        {
            const int w = tid >> 5;
            const uint32_t aH = smem_u32(A2h), aL = smem_u32(A2l);
            const uint32_t bH = smem_u32(B2h), bL = smem_u32(B2l);
            const int ai = lane >> 3, arw = lane & 7;
            const int bl = lane & 15;
            const uint32_t bRowPart = (uint32_t)(bl & 7) * AR2 + (uint32_t)(((bl >> 3) & 1) << 4);

            #pragma unroll
            for (int rep = 0; rep < 2; ++rep) {
                const int mt = w + rep * 8;
                if (mt >= 13) break;
                float C[8][4];
                #pragma unroll
                for (int i = 0; i < 8; ++i)
                    #pragma unroll
                    for (int jj = 0; jj < 4; ++jj) C[i][jj] = 0.f;

                #pragma unroll
                for (int ks = 0; ks < 4; ++ks) {
                    const uint32_t kb = (uint32_t)ks * 32u;
                    uint32_t Ah[4], Al[4];
                    uint32_t ro = (uint32_t)(mt * 16 + ((ai & 1) << 3) + arw) * AR2
                                + (uint32_t)((ai >> 1) << 4) + kb;
                    LDSM4(Ah, aH + ro);
                    LDSM4(Al, aL + ro);
                    #pragma unroll
                    for (int nt = 0; nt < 8; ++nt) {
                        uint32_t rb = (uint32_t)(nt * 8) * AR2 + bRowPart + kb;
                        uint32_t Bh[2], Bl2[2];
                        LDSM2(Bh, bH + rb);
                        LDSM2(Bl2, bL + rb);
                        MMA16816(C[nt], Ah, Bh);
                        MMA16816(C[nt], Al, Bh);
                        MMA16816(C[nt], Ah, Bl2);
                    }
                }

                #pragma unroll
                for (int nt = 0; nt < 8; ++nt) {
                    const int j = nt * 8 + 2 * (lane & 3);
                    const float a0 = a2s[j], a1 = a2s[j + 1];
                    const int r0 = mt * 16 + (lane >> 2);
                    const int r1 = r0 + 8;
                    if (r0 < Nn) {
                        float2 o;
                        o.x = fmaxf(fmaf(C[nt][0], inv, a0), 0.f);
                        o.y = fmaxf(fmaf(C[nt][1], inv, a1), 0.f);
                        *(float2*)&g_h2[((size_t)(b * Nn + r0) * Tn + t) * Hd + j] = o;
                    }
                    if (r1 < Nn) {
                        float2 o;
                        o.x = fmaxf(fmaf(C[nt][2], inv, a0), 0.f);
                        o.y = fmaxf(fmaf(C[nt][3], inv, a1), 0.f);
                        *(float2*)&g_h2[((size_t)(b * Nn + r1) * Tn + t) * Hd + j] = o;
                    }
                }
            }
        }
        __syncthreads();   // protect xs/A2 for next timestep
    }
}

// =====================================================================
// Kernel 2: HMMA LSTM + FC (proven R12 — 369 us at R12 clocks, 6.1e-6).
// 138 CTAs x 384 threads; warp owns 32 rows x 8-unit slice; fp32 gates;
// double-buffered swizzled A; one sync/step; reg-prefetch x.
// =====================================================================
#define LNB  138
#define LNT  384
#define MROW 96
#define ABUF 49152
#define O_B_HI  98304
#define O_B_LO  163840
#define O_BIAS  229376
#define O_WFC   230400
#define O_FCP   230656
#define LSMEM   231040

__device__ __forceinline__ uint32_t aswz(int row, int c16) {
    return (uint32_t)row * 256u
         + (uint32_t)((((c16) ^ (row & 7)) & 7) | ((c16) & 8)) * 16u;
}

__device__ __forceinline__ void load_x(float4* px, int tid, int blk, int t) {
    const int row = tid >> 2, cq = tid & 3;
    const float* gp = g_h2 + ((size_t)(blk * MROW + row) * Tn + t) * Hd + cq * 16;
    px[0] = ((const float4*)gp)[0];
    px[1] = ((const float4*)gp)[1];
    px[2] = ((const float4*)gp)[2];
    px[3] = ((const float4*)gp)[3];
}
__device__ __forceinline__ void store_x(char* Dh, char* Dl, const float4* px, int tid) {
    const int row = tid >> 2, cq = tid & 3;
    float f[16] = { px[0].x, px[0].y, px[0].z, px[0].w,
                    px[1].x, px[1].y, px[1].z, px[1].w,
                    px[2].x, px[2].y, px[2].z, px[2].w,
                    px[3].x, px[3].y, px[3].z, px[3].w };
    unsigned short hh[16], ll[16];
    #pragma unroll
    for (int e = 0; e < 16; ++e) bf16split(f[e], hh[e], ll[e]);
    uint4 H0 = make_uint4((uint32_t)hh[0] | ((uint32_t)hh[1] << 16), (uint32_t)hh[2] | ((uint32_t)hh[3] << 16),
                          (uint32_t)hh[4] | ((uint32_t)hh[5] << 16), (uint32_t)hh[6] | ((uint32_t)hh[7] << 16));
    uint4 H1 = make_uint4((uint32_t)hh[8] | ((uint32_t)hh[9] << 16), (uint32_t)hh[10] | ((uint32_t)hh[11] << 16),
                          (uint32_t)hh[12] | ((uint32_t)hh[13] << 16), (uint32_t)hh[14] | ((uint32_t)hh[15] << 16));
    uint4 L0 = make_uint4((uint32_t)ll[0] | ((uint32_t)ll[1] << 16), (uint32_t)ll[2] | ((uint32_t)ll[3] << 16),
                          (uint32_t)ll[4] | ((uint32_t)ll[5] << 16), (uint32_t)ll[6] | ((uint32_t)ll[7] << 16));
    uint4 L1 = make_uint4((uint32_t)ll[8] | ((uint32_t)ll[9] << 16), (uint32_t)ll[10] | ((uint32_t)ll[11] << 16),
                          (uint32_t)ll[12] | ((uint32_t)ll[13] << 16), (uint32_t)ll[14] | ((uint32_t)ll[15] << 16));
    const uint32_t a0 = aswz(row, cq * 2);
    const uint32_t a1 = aswz(row, cq * 2 + 1);
    *(uint4*)(Dh + a0) = H0;
    *(uint4*)(Dh + a1) = H1;
    *(uint4*)(Dl + a0) = L0;
    *(uint4*)(Dl + a1) = L1;
}

__global__ void __launch_bounds__(LNT, 1) lstm_kernel(
    const float* __restrict__ Wih, const float* __restrict__ Whh,
    const float* __restrict__ bih, const float* __restrict__ bhh,
    const float* __restrict__ Wfc, const float* __restrict__ bfc,
    float* __restrict__ out)
{
    extern __shared__ char smc[];
    char*  Bhi   = smc + O_B_HI;
    char*  Blo   = smc + O_B_LO;
    float* bias2 = (float*)(smc + O_BIAS);
    float* wfcs  = (float*)(smc + O_WFC);
    float* fcp   = (float*)(smc + O_FCP);

    const int tid = threadIdx.x;

    for (int i = tid; i < 256 * 128; i += LNT) {
        int n = i >> 7, k = i & 127;
        float v = (k < 64) ? Wih[n * 64 + k] : Whh[n * 64 + (k - 64)];
        unsigned short hh, ll;
        bf16split(v, hh, ll);
        uint32_t addr = aswz(n, k >> 3) + (uint32_t)((k * 2) & 15);
        *(unsigned short*)(Bhi + addr) = hh;
        *(unsigned short*)(Blo + addr) = ll;
    }
    for (int i = tid; i < (2 * ABUF) / 4; i += LNT) ((uint32_t*)smc)[i] = 0u;
    for (int i = tid; i < 256; i += LNT) {
        int u = i >> 2, g = i & 3;
        float b = bih[g * 64 + u] + bhh[g * 64 + u];
        bias2[i] = (g == 2) ? b : 0.5f * b;
    }
    if (tid < 64) wfcs[tid] = Wfc[tid];
    if (tid < MROW) fcp[tid] = 0.f;
    __syncthreads();

    const int w = tid >> 5, lane = tid & 31;
    const int mp = w % 3;
    const int nq = w / 3;

    const uint32_t sb = smem_u32(smc);
    const uint32_t bH = sb + O_B_HI, bL = sb + O_B_LO;

    const int ai  = lane >> 3;
    const int arw = lane & 7;
    const int aCsel = ai >> 1;
    const uint32_t aBase0 = (uint32_t)(32 * mp + ((ai & 1) << 3) + arw) * 256u;
    const uint32_t aBase1 = aBase0 + 16u * 256u;
    const int bl  = lane & 15;
    const int bCsel = (bl >> 3) & 1;
    const uint32_t bBase = (uint32_t)((nq * 8 + (bl & 7)) * 256);

    float cst[16];
    #pragma unroll
    for (int i = 0; i < 16; ++i) cst[i] = 0.f;

    {
        float4 px0[4];
        load_x(px0, tid, blockIdx.x, 0);
        store_x(smc, smc + 24576, px0, tid);
    }
    __syncthreads();

    for (int t = 0; t < Tn; ++t) {
        const int rbuf = t & 1, wbuf = rbuf ^ 1;
        const uint32_t rdHi = sb + rbuf * ABUF, rdLo = rdHi + 24576;
        const bool last = (t == Tn - 1);

        float4 px[4];
        if (t + 1 < Tn) load_x(px, tid, blockIdx.x, t + 1);

        char* WH = smc + wbuf * ABUF;
        char* WL = WH + 24576;

        #pragma unroll
        for (int p = 0; p < 2; ++p) {
            float C[2][4][4];
            #pragma unroll
            for (int m = 0; m < 2; ++m)
                #pragma unroll
                for (int g = 0; g < 4; ++g)
                    #pragma unroll
                    for (int jj = 0; jj < 4; ++jj) C[m][g][jj] = 0.f;

            #pragma unroll
            for (int ks = 0; ks < 8; ++ks) {
                const int ca = ks * 2 + aCsel;
                const uint32_t swa = (uint32_t)((((ca ^ arw) & 7) | (ca & 8)) << 4);
                const int cb = ks * 2 + bCsel;
                const uint32_t swb = (uint32_t)((((cb ^ (bl & 7)) & 7) | (cb & 8)) << 4);
                uint32_t Ah[2][4], Al[2][4];
                LDSM4(Ah[0], rdHi + aBase0 + swa);
                LDSM4(Al[0], rdLo + aBase0 + swa);
                LDSM4(Ah[1], rdHi + aBase1 + swa);
                LDSM4(Al[1], rdLo + aBase1 + swa);
                #pragma unroll
                for (int g = 0; g < 4; ++g) {
                    const uint32_t bo = bBase + (uint32_t)(g * 16384 + p * 8192) + swb;
                    uint32_t Bh[2], Bl2[2];
                    LDSM2(Bh, bH + bo);
                    MMA16816(C[0][g], Ah[0], Bh);
                    MMA16816(C[1][g], Ah[1], Bh);
                    MMA16816(C[0][g], Al[0], Bh);
                    MMA16816(C[1][g], Al[1], Bh);
                    LDSM2(Bl2, bL + bo);
                    MMA16816(C[0][g], Ah[0], Bl2);
                    MMA16816(C[1][g], Ah[1], Bl2);
                }
            }

            const int c16 = 8 + p * 4 + nq;
            #pragma unroll
            for (int m = 0; m < 2; ++m)
                #pragma unroll
                for (int rh = 0; rh < 2; ++rh) {
                    const int row = 32 * mp + 16 * m + 8 * rh + (lane >> 2);
                    const uint32_t off = (uint32_t)row * 256u
                        + (uint32_t)((((c16 ^ (row & 7)) & 7) | 8) << 4)
                        + (uint32_t)(4 * (lane & 3));
                    uint32_t hiw = 0u, low = 0u;
                    #pragma unroll
                    for (int e = 0; e < 2; ++e) {
                        const int u = p * 32 + nq * 8 + 2 * (lane & 3) + e;
                        const float4 bb = *(const float4*)(bias2 + 4 * u);
                        const int idx4 = rh * 2 + e;
                        const float gi = C[m][0][idx4];
                        const float gf = C[m][1][idx4];
                        const float gg = C[m][2][idx4];
                        const float go = C[m][3][idx4];
                        const float ig = sigm2(gi, bb.x);
                        const float fg = sigm2(gf, bb.y);
                        const float g_ = tanhm(gg + bb.z);
                        const float og = sigm2(go, bb.w);
                        const int ci = ((p * 2 + m) * 2 + rh) * 2 + e;
                        const float cn = fmaf(fg, cst[ci], ig * g_);
                        cst[ci] = cn;
                        const float hv = og * tanhm(cn);
                        unsigned short hh, ll;
                        bf16split(hv, hh, ll);
                        hiw |= ((uint32_t)hh) << (16 * e);
                        low |= ((uint32_t)ll) << (16 * e);
                        if (last) atomicAdd(&fcp[row], hv * wfcs[u]);
                    }
                    *(uint32_t*)(WH + off) = hiw;
                    *(uint32_t*)(WL + off) = low;
                }
        }

        if (t + 1 < Tn) store_x(WH, WL, px, tid);
        __syncthreads();
    }

    if (tid < MROW) out[blockIdx.x * MROW + tid] = fcp[tid] + bfc[0];
}

// =====================================================================
extern "C" void kernel_launch(void* const* d_in, const int* in_sizes, int n_in,
                              void* d_out, int out_size)
{
    const float* x   = (const float*)d_in[0];
    // d_in[1], d_in[2] = N1, N2: structurally irrelevant (sigmoid > 0 everywhere)
    const float* W1  = (const float*)d_in[3];
    const float* b1  = (const float*)d_in[4];
    const float* W2  = (const float*)d_in[5];
    const float* b2  = (const float*)d_in[6];
    const float* Wih = (const float*)d_in[7];
    const float* Whh = (const float*)d_in[8];
    const float* bih = (const float*)d_in[9];
    const float* bhh = (const float*)d_in[10];
    const float* Wfc = (const float*)d_in[11];
    const float* bfc = (const float*)d_in[12];
    float* out = (float*)d_out;

    cudaFuncSetAttribute(gcn_kernel,  cudaFuncAttributeMaxDynamicSharedMemorySize, G_SMEM);
    cudaFuncSetAttribute(lstm_kernel, cudaFuncAttributeMaxDynamicSharedMemorySize, LSMEM);

    gcn_kernel<<<dim3(Tn / 4, Bn), 256, G_SMEM>>>(x, W1, b1, W2, b2);
    lstm_kernel<<<LNB, LNT, LSMEM>>>(Wih, Whh, bih, bhh, Wfc, bfc, out);
}